// round 1
// baseline (speedup 1.0000x reference)
#include <cuda_runtime.h>
#include <math.h>

// Problem constants (fixed by setup_inputs)
#define BB 2
#define NN 16384
#define MQ 4096
#define C1 128
#define C2 256
#define VC 387          // 3 + 128 + 256 per-query channels
#define GC 1024         // global feature channels
#define CT 1411         // total channels
#define S 8             // N-chunks for kNN
#define CHUNK (NN / S)  // 2048
#define QPB 128         // queries per kNN block

// ---------------- scratch (static device memory; no allocations) -------------
__device__ float g_pd[BB * MQ * S * 3];   // partial top-3 relative distances
__device__ int   g_pi[BB * MQ * S * 3];   // partial top-3 indices
__device__ float g_w [BB * MQ * 3];       // normalized Gaussian weights
__device__ int   g_i [BB * MQ * 3];       // final kNN indices
__device__ float g_vals[BB * MQ * VC];    // per-query channel vector [b,m,0..386]

#define FINF __int_as_float(0x7f800000)

// ---------------- kernel 1: partial kNN over one N-chunk --------------------
__global__ void __launch_bounds__(QPB) knn_kernel(const float* __restrict__ P,
                                                  const float* __restrict__ Q) {
    __shared__ float4 sp[CHUNK];   // (-2px, -2py, -2pz, p2)

    const int nmblk = MQ / QPB;                 // 32
    int blk  = blockIdx.x;
    int mblk = blk % nmblk;
    int s    = (blk / nmblk) % S;
    int b    = blk / (nmblk * S);
    int n0   = s * CHUNK;

    const float* Pb = P + b * 3 * NN;
    for (int j = threadIdx.x; j < CHUNK; j += QPB) {
        float px = Pb[n0 + j];
        float py = Pb[NN + n0 + j];
        float pz = Pb[2 * NN + n0 + j];
        sp[j] = make_float4(-2.0f * px, -2.0f * py, -2.0f * pz,
                            px * px + py * py + pz * pz);
    }
    __syncthreads();

    int m = mblk * QPB + threadIdx.x;
    const float* Qb = Q + b * 3 * MQ;
    float qx = Qb[m], qy = Qb[MQ + m], qz = Qb[2 * MQ + m];

    float d0 = FINF, d1 = FINF, d2v = FINF;
    int   i0 = 0,   i1 = 0,   i2 = 0;

#pragma unroll 8
    for (int j = 0; j < CHUNK; j++) {
        float4 p = sp[j];
        float t = fmaf(qx, p.x, p.w);
        t = fmaf(qy, p.y, t);
        t = fmaf(qz, p.z, t);
        if (t < d2v) {                       // rare after warm-up
            int n = n0 + j;
            if (t < d1) {
                d2v = d1; i2 = i1;
                if (t < d0) { d1 = d0; i1 = i0; d0 = t; i0 = n; }
                else        { d1 = t;  i1 = n; }
            } else { d2v = t; i2 = n; }
        }
    }

    int o = ((b * MQ + m) * S + s) * 3;
    g_pd[o] = d0;  g_pd[o + 1] = d1;  g_pd[o + 2] = d2v;
    g_pi[o] = i0;  g_pi[o + 1] = i1;  g_pi[o + 2] = i2;
}

// ---------------- kernel 2: merge partials + Gaussian weights ----------------
__global__ void merge_kernel() {
    int t = blockIdx.x * blockDim.x + threadIdx.x;   // b*MQ + m
    if (t >= BB * MQ) return;

    float d0 = FINF, d1 = FINF, d2v = FINF;
    int   i0 = 0,   i1 = 0,   i2 = 0;
    int base = t * S * 3;
#pragma unroll
    for (int j = 0; j < S * 3; j++) {
        float d = g_pd[base + j];
        int   n = g_pi[base + j];
        if (d < d2v) {
            if (d < d1) {
                d2v = d1; i2 = i1;
                if (d < d0) { d1 = d0; i1 = i0; d0 = d; i0 = n; }
                else        { d1 = d;  i1 = n; }
            } else { d2v = d; i2 = n; }
        }
    }
    // weights: exp(-dist2/2) normalized; the per-query constant q2 cancels,
    // so relative distances suffice. Stabilize against d0.
    float e0 = 1.0f;
    float e1 = expf(-0.5f * (d1  - d0));
    float e2 = expf(-0.5f * (d2v - d0));
    float inv = 1.0f / (e0 + e1 + e2);
    g_w[t * 3]     = e0 * inv;
    g_w[t * 3 + 1] = e1 * inv;
    g_w[t * 3 + 2] = e2 * inv;
    g_i[t * 3]     = i0;
    g_i[t * 3 + 1] = i1;
    g_i[t * 3 + 2] = i2;
}

// ---------------- kernel 3: interpolation -> per-query channel vector -------
__global__ void __launch_bounds__(128) interp_kernel(const float* __restrict__ Q,
                                                     const float* __restrict__ F1,
                                                     const float* __restrict__ F2) {
    int bm = blockIdx.x;            // b*MQ + m
    int b  = bm / MQ;
    int m  = bm % MQ;

    __shared__ float sw[3];
    __shared__ int   si[3];
    if (threadIdx.x < 3) {
        sw[threadIdx.x] = g_w[bm * 3 + threadIdx.x];
        si[threadIdx.x] = g_i[bm * 3 + threadIdx.x];
    }
    __syncthreads();
    float w0 = sw[0], w1 = sw[1], w2 = sw[2];
    int   i0 = si[0], i1 = si[1], i2 = si[2];

    float* v = g_vals + (long)bm * VC;

    if (threadIdx.x < 3)
        v[threadIdx.x] = Q[(b * 3 + threadIdx.x) * MQ + m];

    {   // feat1: 128 channels, one per thread
        int c = threadIdx.x;
        const float* f = F1 + ((long)(b * C1 + c)) * NN;
        v[3 + c] = w0 * f[i0] + w1 * f[i1] + w2 * f[i2];
    }
#pragma unroll
    for (int c = threadIdx.x; c < C2; c += 128) {   // feat2: 256 channels
        const float* f = F2 + ((long)(b * C2 + c)) * NN;
        v[3 + C1 + c] = w0 * f[i0] + w1 * f[i1] + w2 * f[i2];
    }
}

// ---------------- kernel 4: adaptive max pool + output write ----------------
#define RPB 4
__global__ void __launch_bounds__(256) pool_kernel(const float* __restrict__ G,
                                                   float* __restrict__ out) {
    __shared__ float sv[RPB][VC];
    __shared__ float sg[GC];

    int blk = blockIdx.x;                 // 0 .. B*MQ/RPB - 1
    int b   = blk / (MQ / RPB);
    int m0  = (blk % (MQ / RPB)) * RPB;

    for (int j = threadIdx.x; j < GC; j += blockDim.x)
        sg[j] = G[b * GC + j];
    for (int j = threadIdx.x; j < RPB * VC; j += blockDim.x) {
        int r = j / VC, c = j % VC;
        sv[r][c] = g_vals[((long)(b * MQ + m0 + r)) * VC + c];
    }
    __syncthreads();

#pragma unroll
    for (int r = 0; r < RPB; r++) {
        float* orow = out + ((long)(b * MQ + m0 + r)) * MQ;
        for (int i = threadIdx.x; i < MQ; i += blockDim.x) {
            int st = (i * CT) >> 12;                       // floor(i*1411/4096)
            int en = ((i + 1) * CT + 4095) >> 12;          // ceil((i+1)*1411/4096)
            float a = (st < VC) ? sv[r][st] : sg[st - VC];
            if (en - st == 2) {
                int s1 = st + 1;
                float c = (s1 < VC) ? sv[r][s1] : sg[s1 - VC];
                a = fmaxf(a, c);
            }
            orow[i] = a;
        }
    }
}

// ---------------- launch -----------------------------------------------------
extern "C" void kernel_launch(void* const* d_in, const int* in_sizes, int n_in,
                              void* d_out, int out_size) {
    const float* P  = (const float*)d_in[0];   // original_pts [B,3,N]
    const float* Q  = (const float*)d_in[1];   // query_pts    [B,3,M]
    const float* F1 = (const float*)d_in[2];   // local_feat1  [B,128,N]
    const float* F2 = (const float*)d_in[3];   // local_feat2  [B,256,N]
    const float* G  = (const float*)d_in[4];   // global_feats [B,1024]
    float* out = (float*)d_out;                // [B,M,M]

    knn_kernel<<<BB * S * (MQ / QPB), QPB>>>(P, Q);
    merge_kernel<<<(BB * MQ + 255) / 256, 256>>>();
    interp_kernel<<<BB * MQ, 128>>>(Q, F1, F2);
    pool_kernel<<<BB * MQ / RPB, 256>>>(G, out);
}

// round 2
// speedup vs baseline: 1.0998x; 1.0998x over previous
#include <cuda_runtime.h>
#include <math.h>

// Problem constants (fixed by setup_inputs)
#define BB 2
#define NN 16384
#define MQ 4096
#define C1 128
#define C2 256
#define FC 384          // feature channels (128 + 256)
#define VC 387          // 3 coords + 384 features (logical per-query channels)
#define VS 388          // padded row stride of g_vals (16B-aligned float4 rows)
#define GC 1024         // global feature channels
#define CT 1411         // total channels
#define VCOLS 1124      // output columns whose window touches per-query channels
#define GCOLS (MQ - VCOLS)   // 2972 columns depending only on global feats
#define S 8             // N-chunks for kNN
#define CHUNK (NN / S)  // 2048
#define QPB 128         // queries per kNN block

// ---------------- scratch (static device memory; no allocations) -------------
__device__ float  g_pd[BB * MQ * S * 3];   // partial top-3 relative distances
__device__ int    g_pi[BB * MQ * S * 3];   // partial top-3 indices
__device__ float  g_w [BB * MQ * 3];       // normalized Gaussian weights
__device__ int    g_i [BB * MQ * 3];       // final kNN indices
__device__ float  g_vals[BB * MQ * VS];    // per-query: [0..383]=feat, [384..386]=coords
__device__ float  g_ft[(long)BB * NN * FC];// transposed features [b][n][c]
__device__ float4 g_grow[BB][GCOLS / 4];   // per-batch pooled global segment (743 f4)

#define FINF __int_as_float(0x7f800000)

// ---------------- kernel 0: feature transpose [B,C,N] -> g_ft[b][n][coff+c] --
__global__ void __launch_bounds__(256) transpose_kernel(const float* __restrict__ F,
                                                        int C, int coff) {
    __shared__ float tile[32][33];
    int b  = blockIdx.z;
    int n0 = blockIdx.x * 32;
    int c0 = blockIdx.y * 32;
    int tx = threadIdx.x & 31;
    int ty = threadIdx.x >> 5;           // 0..7

#pragma unroll
    for (int r = ty; r < 32; r += 8)
        tile[r][tx] = F[((long)(b * C + c0 + r)) * NN + n0 + tx];
    __syncthreads();
#pragma unroll
    for (int r = ty; r < 32; r += 8) {
        int n = n0 + r, c = c0 + tx;
        g_ft[((long)(b * NN + n)) * FC + coff + c] = tile[tx][r];
    }
}

// ---------------- kernel 1: partial kNN over one N-chunk --------------------
__global__ void __launch_bounds__(QPB) knn_kernel(const float* __restrict__ P,
                                                  const float* __restrict__ Q) {
    __shared__ float4 sp[CHUNK];   // (-2px, -2py, -2pz, p2)

    const int nmblk = MQ / QPB;                 // 32
    int blk  = blockIdx.x;
    int mblk = blk % nmblk;
    int s    = (blk / nmblk) % S;
    int b    = blk / (nmblk * S);
    int n0   = s * CHUNK;

    const float* Pb = P + b * 3 * NN;
    for (int j = threadIdx.x; j < CHUNK; j += QPB) {
        float px = Pb[n0 + j];
        float py = Pb[NN + n0 + j];
        float pz = Pb[2 * NN + n0 + j];
        sp[j] = make_float4(-2.0f * px, -2.0f * py, -2.0f * pz,
                            px * px + py * py + pz * pz);
    }
    __syncthreads();

    int m = mblk * QPB + threadIdx.x;
    const float* Qb = Q + b * 3 * MQ;
    float qx = Qb[m], qy = Qb[MQ + m], qz = Qb[2 * MQ + m];

    float d0 = FINF, d1 = FINF, d2v = FINF;
    int   i0 = 0,   i1 = 0,   i2 = 0;

#pragma unroll 8
    for (int j = 0; j < CHUNK; j++) {
        float4 p = sp[j];
        float t = fmaf(qx, p.x, p.w);
        t = fmaf(qy, p.y, t);
        t = fmaf(qz, p.z, t);
        if (t < d2v) {                       // rare after warm-up
            int n = n0 + j;
            if (t < d1) {
                d2v = d1; i2 = i1;
                if (t < d0) { d1 = d0; i1 = i0; d0 = t; i0 = n; }
                else        { d1 = t;  i1 = n; }
            } else { d2v = t; i2 = n; }
        }
    }

    int o = ((b * MQ + m) * S + s) * 3;
    g_pd[o] = d0;  g_pd[o + 1] = d1;  g_pd[o + 2] = d2v;
    g_pi[o] = i0;  g_pi[o + 1] = i1;  g_pi[o + 2] = i2;
}

// ---------------- kernel 2: merge partials + Gaussian weights ----------------
__global__ void merge_kernel() {
    int t = blockIdx.x * blockDim.x + threadIdx.x;   // b*MQ + m
    if (t >= BB * MQ) return;

    float d0 = FINF, d1 = FINF, d2v = FINF;
    int   i0 = 0,   i1 = 0,   i2 = 0;
    int base = t * S * 3;
#pragma unroll
    for (int j = 0; j < S * 3; j++) {
        float d = g_pd[base + j];
        int   n = g_pi[base + j];
        if (d < d2v) {
            if (d < d1) {
                d2v = d1; i2 = i1;
                if (d < d0) { d1 = d0; i1 = i0; d0 = d; i0 = n; }
                else        { d1 = d;  i1 = n; }
            } else { d2v = d; i2 = n; }
        }
    }
    // exp(-dist2/2) normalized; per-query constant q2 cancels. Stabilize at d0.
    float e0 = 1.0f;
    float e1 = expf(-0.5f * (d1  - d0));
    float e2 = expf(-0.5f * (d2v - d0));
    float inv = 1.0f / (e0 + e1 + e2);
    g_w[t * 3]     = e0 * inv;
    g_w[t * 3 + 1] = e1 * inv;
    g_w[t * 3 + 2] = e2 * inv;
    g_i[t * 3]     = i0;
    g_i[t * 3 + 1] = i1;
    g_i[t * 3 + 2] = i2;
}

// ---------------- kernel 3: interpolation (coalesced via g_ft) ---------------
__global__ void __launch_bounds__(128) interp_kernel(const float* __restrict__ Q) {
    int bm = blockIdx.x;            // b*MQ + m
    int b  = bm / MQ;
    int m  = bm % MQ;

    __shared__ float sw[3];
    __shared__ int   si[3];
    if (threadIdx.x < 3) {
        sw[threadIdx.x] = g_w[bm * 3 + threadIdx.x];
        si[threadIdx.x] = g_i[bm * 3 + threadIdx.x];
    }
    __syncthreads();
    float w0 = sw[0], w1 = sw[1], w2 = sw[2];
    const float4* f0 = (const float4*)(g_ft + ((long)(b * NN + si[0])) * FC);
    const float4* f1 = (const float4*)(g_ft + ((long)(b * NN + si[1])) * FC);
    const float4* f2 = (const float4*)(g_ft + ((long)(b * NN + si[2])) * FC);

    float* v = g_vals + (long)bm * VS;
    if (threadIdx.x < 3)
        v[FC + threadIdx.x] = Q[(b * 3 + threadIdx.x) * MQ + m];

    int c4 = threadIdx.x;
    if (c4 < FC / 4) {              // 96 float4 lanes
        float4 a = f0[c4], bb = f1[c4], cc = f2[c4];
        float4 r;
        r.x = w0 * a.x + w1 * bb.x + w2 * cc.x;
        r.y = w0 * a.y + w1 * bb.y + w2 * cc.y;
        r.z = w0 * a.z + w1 * bb.z + w2 * cc.z;
        r.w = w0 * a.w + w1 * bb.w + w2 * cc.w;
        ((float4*)v)[c4] = r;
    }
}

// ---------------- kernel 3b: per-batch pooled global segment -----------------
__global__ void __launch_bounds__(1024) gpool_kernel(const float* __restrict__ G) {
    __shared__ float sg[GC];
    int b = blockIdx.x;
    for (int j = threadIdx.x; j < GC; j += blockDim.x)
        sg[j] = G[b * GC + j];
    __syncthreads();
    for (int i = VCOLS + threadIdx.x; i < MQ; i += blockDim.x) {
        int st = (i * CT) >> 12;
        int en = ((i + 1) * CT + 4095) >> 12;
        float a = sg[st - VC];
        if (en - st == 2) a = fmaxf(a, sg[st + 1 - VC]);
        ((float*)g_grow[b])[i - VCOLS] = a;
    }
}

// ---------------- kernel 4: adaptive max pool + output write ----------------
#define RPB 4
__global__ void __launch_bounds__(256) pool_kernel(const float* __restrict__ G,
                                                   float* __restrict__ out) {
    __shared__ float sv[RPB][VC];   // logical order: [0..2]=coords, [3..386]=feat

    int blk = blockIdx.x;                 // 0 .. B*MQ/RPB - 1
    int b   = blk / (MQ / RPB);
    int m0  = (blk % (MQ / RPB)) * RPB;
    float sg0 = G[b * GC];                // only global channel reachable in i<VCOLS

    for (int j = threadIdx.x; j < RPB * VC; j += 256) {
        int r = j / VC, ch = j % VC;
        const float* row = g_vals + (long)(b * MQ + m0 + r) * VS;
        sv[r][ch] = (ch < 3) ? row[FC + ch] : row[ch - 3];
    }
    __syncthreads();

    const float4* gr = g_grow[b];
#pragma unroll
    for (int r = 0; r < RPB; r++) {
        float* orow = out + ((long)(b * MQ + m0 + r)) * MQ;
        // segment A: columns [0, VCOLS): per-row window math, float4 stores
        for (int q = threadIdx.x; q < VCOLS / 4; q += 256) {
            float4 o;
            float* op = (float*)&o;
#pragma unroll
            for (int u = 0; u < 4; u++) {
                int i  = q * 4 + u;
                int st = (i * CT) >> 12;
                int en = ((i + 1) * CT + 4095) >> 12;
                float a = sv[r][st];
                if (en - st == 2) {
                    int s1 = st + 1;
                    float c = (s1 < VC) ? sv[r][s1] : sg0;
                    a = fmaxf(a, c);
                }
                op[u] = a;
            }
            ((float4*)orow)[q] = o;
        }
        // segment B: columns [VCOLS, MQ): batch-constant, vectorized copy
        float4* od = (float4*)(orow + VCOLS);
        for (int q = threadIdx.x; q < GCOLS / 4; q += 256)
            od[q] = gr[q];
    }
}

// ---------------- launch -----------------------------------------------------
extern "C" void kernel_launch(void* const* d_in, const int* in_sizes, int n_in,
                              void* d_out, int out_size) {
    const float* P  = (const float*)d_in[0];   // original_pts [B,3,N]
    const float* Q  = (const float*)d_in[1];   // query_pts    [B,3,M]
    const float* F1 = (const float*)d_in[2];   // local_feat1  [B,128,N]
    const float* F2 = (const float*)d_in[3];   // local_feat2  [B,256,N]
    const float* G  = (const float*)d_in[4];   // global_feats [B,1024]
    float* out = (float*)d_out;                // [B,M,M]

    dim3 tg1(NN / 32, C1 / 32, BB);
    dim3 tg2(NN / 32, C2 / 32, BB);
    transpose_kernel<<<tg1, 256>>>(F1, C1, 0);
    transpose_kernel<<<tg2, 256>>>(F2, C2, C1);
    gpool_kernel<<<BB, 1024>>>(G);
    knn_kernel<<<BB * S * (MQ / QPB), QPB>>>(P, Q);
    merge_kernel<<<(BB * MQ + 255) / 256, 256>>>();
    interp_kernel<<<BB * MQ, 128>>>(Q);
    pool_kernel<<<BB * MQ / RPB, 256>>>(G, out);
}

// round 3
// speedup vs baseline: 1.1275x; 1.0252x over previous
#include <cuda_runtime.h>
#include <math.h>

// Problem constants (fixed by setup_inputs)
#define BB 2
#define NN 16384
#define MQ 4096
#define C1 128
#define C2 256
#define FC 384          // feature channels (128 + 256)
#define VC 387          // 3 coords + 384 features (logical per-query channels)
#define VS 388          // padded row stride of g_vals
#define GC 1024         // global feature channels
#define CT 1411         // total channels
#define VCOLS 1124      // output columns whose window touches per-query channels
#define GCOLS (MQ - VCOLS)   // 2972 columns depending only on global feats
#define S 16            // N-chunks for kNN
#define CHUNK (NN / S)  // 1024
#define QPB 256         // queries per kNN block

// ---------------- scratch (static device memory; no allocations) -------------
__device__ float  g_pd[BB * MQ * S * 3];   // partial top-3 relative distances
__device__ int    g_pi[BB * MQ * S * 3];   // partial top-3 indices
__device__ float  g_w [BB * MQ * 3];       // normalized Gaussian weights
__device__ int    g_i [BB * MQ * 3];       // final kNN indices
__device__ float  g_vals[BB * MQ * VS];    // per-query: [0..383]=feat, [384..386]=coords
__device__ float  g_ft[(long)BB * NN * FC];// transposed features [b][n][c]
__device__ float4 g_grow[BB][GCOLS / 4];   // per-batch pooled global segment

#define FINF __int_as_float(0x7f800000)

// Blackwell packed fp32 pair FMA (2 floats per 64-bit reg)
#define FMA2(d, a, b, c) \
    asm("fma.rn.f32x2 %0, %1, %2, %3;" : "=l"(d) : "l"(a), "l"(b), "l"(c))
#define PACK1X2(d, f) \
    asm("mov.b64 %0, {%1, %1};" : "=l"(d) : "r"(__float_as_uint(f)))

// ---------------- kernel 0: feature transpose [B,C,N] -> g_ft[b][n][coff+c] --
__global__ void __launch_bounds__(256) transpose_kernel(const float* __restrict__ F,
                                                        int C, int coff) {
    __shared__ float tile[32][33];
    int b  = blockIdx.z;
    int n0 = blockIdx.x * 32;
    int c0 = blockIdx.y * 32;
    int tx = threadIdx.x & 31;
    int ty = threadIdx.x >> 5;

#pragma unroll
    for (int r = ty; r < 32; r += 8)
        tile[r][tx] = F[((long)(b * C + c0 + r)) * NN + n0 + tx];
    __syncthreads();
#pragma unroll
    for (int r = ty; r < 32; r += 8) {
        int n = n0 + r, c = c0 + tx;
        g_ft[((long)(b * NN + n)) * FC + coff + c] = tile[tx][r];
    }
}

// ---------------- kernel 1: partial kNN over one N-chunk (f32x2 packed) -----
#define INS3(t, n)                                                \
    do {                                                          \
        if ((t) < d1) {                                           \
            d2v = d1; i2 = i1;                                    \
            if ((t) < d0) { d1 = d0; i1 = i0; d0 = (t); i0 = (n); } \
            else          { d1 = (t); i1 = (n); }                 \
        } else { d2v = (t); i2 = (n); }                           \
    } while (0)

__global__ void __launch_bounds__(QPB) knn_kernel(const float* __restrict__ P,
                                                  const float* __restrict__ Q) {
    // per point-pair jp: sA = (-2x0,-2x1,-2y0,-2y1), sB = (-2z0,-2z1,p2_0,p2_1)
    __shared__ float4 sA[CHUNK / 2];
    __shared__ float4 sB[CHUNK / 2];

    const int nmblk = MQ / QPB;                 // 16
    int blk  = blockIdx.x;
    int mblk = blk % nmblk;
    int s    = (blk / nmblk) % S;
    int b    = blk / (nmblk * S);
    int n0   = s * CHUNK;

    const float* Pb = P + b * 3 * NN;
    for (int jp = threadIdx.x; jp < CHUNK / 2; jp += QPB) {
        int j = n0 + 2 * jp;
        float x0 = Pb[j],          x1 = Pb[j + 1];
        float y0 = Pb[NN + j],     y1 = Pb[NN + j + 1];
        float z0 = Pb[2 * NN + j], z1 = Pb[2 * NN + j + 1];
        sA[jp] = make_float4(-2.f * x0, -2.f * x1, -2.f * y0, -2.f * y1);
        sB[jp] = make_float4(-2.f * z0, -2.f * z1,
                             x0 * x0 + y0 * y0 + z0 * z0,
                             x1 * x1 + y1 * y1 + z1 * z1);
    }
    __syncthreads();

    int m = mblk * QPB + threadIdx.x;
    const float* Qb = Q + b * 3 * MQ;
    unsigned long long qx2, qy2, qz2;
    PACK1X2(qx2, Qb[m]);
    PACK1X2(qy2, Qb[MQ + m]);
    PACK1X2(qz2, Qb[2 * MQ + m]);

    float d0 = FINF, d1 = FINF, d2v = FINF;
    int   i0 = 0,   i1 = 0,   i2 = 0;

    const ulonglong2* pA = (const ulonglong2*)sA;
    const ulonglong2* pB = (const ulonglong2*)sB;

#pragma unroll 4
    for (int jp = 0; jp < CHUNK / 2; jp++) {
        ulonglong2 a  = pA[jp];     // a.x={x0,x1}*-2, a.y={y0,y1}*-2
        ulonglong2 bb = pB[jp];     // bb.x={z0,z1}*-2, bb.y={p2_0,p2_1}
        unsigned long long t;
        FMA2(t, qx2, a.x, bb.y);
        FMA2(t, qy2, a.y, t);
        FMA2(t, qz2, bb.x, t);
        unsigned int lo, hi;
        asm("mov.b64 {%0, %1}, %2;" : "=r"(lo), "=r"(hi) : "l"(t));
        float t0 = __uint_as_float(lo);
        float t1 = __uint_as_float(hi);
        if (fminf(t0, t1) < d2v) {          // rare after warm-up
            int n = n0 + 2 * jp;
            if (t0 < d2v) INS3(t0, n);
            if (t1 < d2v) INS3(t1, n + 1);
        }
    }

    int o = ((b * MQ + m) * S + s) * 3;
    g_pd[o] = d0;  g_pd[o + 1] = d1;  g_pd[o + 2] = d2v;
    g_pi[o] = i0;  g_pi[o + 1] = i1;  g_pi[o + 2] = i2;
}

// ---------------- kernel 2: merge partials + Gaussian weights ----------------
__global__ void merge_kernel() {
    int t = blockIdx.x * blockDim.x + threadIdx.x;   // b*MQ + m
    if (t >= BB * MQ) return;

    float d0 = FINF, d1 = FINF, d2v = FINF;
    int   i0 = 0,   i1 = 0,   i2 = 0;
    int base = t * S * 3;
#pragma unroll
    for (int j = 0; j < S * 3; j++) {
        float d = g_pd[base + j];
        int   n = g_pi[base + j];
        if (d < d2v) {
            if (d < d1) {
                d2v = d1; i2 = i1;
                if (d < d0) { d1 = d0; i1 = i0; d0 = d; i0 = n; }
                else        { d1 = d;  i1 = n; }
            } else { d2v = d; i2 = n; }
        }
    }
    float e0 = 1.0f;
    float e1 = expf(-0.5f * (d1  - d0));
    float e2 = expf(-0.5f * (d2v - d0));
    float inv = 1.0f / (e0 + e1 + e2);
    g_w[t * 3]     = e0 * inv;
    g_w[t * 3 + 1] = e1 * inv;
    g_w[t * 3 + 2] = e2 * inv;
    g_i[t * 3]     = i0;
    g_i[t * 3 + 1] = i1;
    g_i[t * 3 + 2] = i2;
}

// ---------------- kernel 3: interpolation (coalesced via g_ft) ---------------
__global__ void __launch_bounds__(128) interp_kernel(const float* __restrict__ Q) {
    int bm = blockIdx.x;            // b*MQ + m
    int b  = bm / MQ;
    int m  = bm % MQ;

    __shared__ float sw[3];
    __shared__ int   si[3];
    if (threadIdx.x < 3) {
        sw[threadIdx.x] = g_w[bm * 3 + threadIdx.x];
        si[threadIdx.x] = g_i[bm * 3 + threadIdx.x];
    }
    __syncthreads();
    float w0 = sw[0], w1 = sw[1], w2 = sw[2];
    const float4* f0 = (const float4*)(g_ft + ((long)(b * NN + si[0])) * FC);
    const float4* f1 = (const float4*)(g_ft + ((long)(b * NN + si[1])) * FC);
    const float4* f2 = (const float4*)(g_ft + ((long)(b * NN + si[2])) * FC);

    float* v = g_vals + (long)bm * VS;
    if (threadIdx.x < 3)
        v[FC + threadIdx.x] = Q[(b * 3 + threadIdx.x) * MQ + m];

    int c4 = threadIdx.x;
    if (c4 < FC / 4) {              // 96 float4 lanes
        float4 a = f0[c4], bb = f1[c4], cc = f2[c4];
        float4 r;
        r.x = w0 * a.x + w1 * bb.x + w2 * cc.x;
        r.y = w0 * a.y + w1 * bb.y + w2 * cc.y;
        r.z = w0 * a.z + w1 * bb.z + w2 * cc.z;
        r.w = w0 * a.w + w1 * bb.w + w2 * cc.w;
        ((float4*)v)[c4] = r;
    }
}

// ---------------- kernel 3b: per-batch pooled global segment -----------------
__global__ void __launch_bounds__(1024) gpool_kernel(const float* __restrict__ G) {
    __shared__ float sg[GC];
    int b = blockIdx.x;
    for (int j = threadIdx.x; j < GC; j += blockDim.x)
        sg[j] = G[b * GC + j];
    __syncthreads();
    for (int i = VCOLS + threadIdx.x; i < MQ; i += blockDim.x) {
        int st = (i * CT) >> 12;
        int en = ((i + 1) * CT + 4095) >> 12;
        float a = sg[st - VC];
        if (en - st == 2) a = fmaxf(a, sg[st + 1 - VC]);
        ((float*)g_grow[b])[i - VCOLS] = a;
    }
}

// ---------------- kernel 4: adaptive max pool + output write ----------------
#define RPB 4
__global__ void __launch_bounds__(256) pool_kernel(const float* __restrict__ G,
                                                   float* __restrict__ out) {
    __shared__ float sv[RPB][VC];   // logical order: [0..2]=coords, [3..386]=feat

    int blk = blockIdx.x;                 // 0 .. B*MQ/RPB - 1
    int b   = blk / (MQ / RPB);
    int m0  = (blk % (MQ / RPB)) * RPB;
    float sg0 = G[b * GC];                // only global channel reachable in i<VCOLS

    for (int j = threadIdx.x; j < RPB * VC; j += 256) {
        int r = j / VC, ch = j % VC;
        const float* row = g_vals + (long)(b * MQ + m0 + r) * VS;
        sv[r][ch] = (ch < 3) ? row[FC + ch] : row[ch - 3];
    }
    __syncthreads();

    const float4* gr = g_grow[b];
#pragma unroll
    for (int r = 0; r < RPB; r++) {
        float* orow = out + ((long)(b * MQ + m0 + r)) * MQ;
        for (int q = threadIdx.x; q < VCOLS / 4; q += 256) {
            float4 o;
            float* op = (float*)&o;
#pragma unroll
            for (int u = 0; u < 4; u++) {
                int i  = q * 4 + u;
                int st = (i * CT) >> 12;
                int en = ((i + 1) * CT + 4095) >> 12;
                float a = sv[r][st];
                if (en - st == 2) {
                    int s1 = st + 1;
                    float c = (s1 < VC) ? sv[r][s1] : sg0;
                    a = fmaxf(a, c);
                }
                op[u] = a;
            }
            ((float4*)orow)[q] = o;
        }
        float4* od = (float4*)(orow + VCOLS);
        for (int q = threadIdx.x; q < GCOLS / 4; q += 256)
            od[q] = gr[q];
    }
}

// ---------------- launch -----------------------------------------------------
extern "C" void kernel_launch(void* const* d_in, const int* in_sizes, int n_in,
                              void* d_out, int out_size) {
    const float* P  = (const float*)d_in[0];   // original_pts [B,3,N]
    const float* Q  = (const float*)d_in[1];   // query_pts    [B,3,M]
    const float* F1 = (const float*)d_in[2];   // local_feat1  [B,128,N]
    const float* F2 = (const float*)d_in[3];   // local_feat2  [B,256,N]
    const float* G  = (const float*)d_in[4];   // global_feats [B,1024]
    float* out = (float*)d_out;                // [B,M,M]

    dim3 tg1(NN / 32, C1 / 32, BB);
    dim3 tg2(NN / 32, C2 / 32, BB);
    transpose_kernel<<<tg1, 256>>>(F1, C1, 0);
    transpose_kernel<<<tg2, 256>>>(F2, C2, C1);
    gpool_kernel<<<BB, 1024>>>(G);
    knn_kernel<<<BB * S * (MQ / QPB), QPB>>>(P, Q);
    merge_kernel<<<(BB * MQ + 255) / 256, 256>>>();
    interp_kernel<<<BB * MQ, 128>>>(Q);
    pool_kernel<<<BB * MQ / RPB, 256>>>(G, out);
}